// round 2
// baseline (speedup 1.0000x reference)
#include <cuda_runtime.h>
#include <cstdint>

// Problem constants
#define BATCH   20000
#define NNB     20
#define NODE_D  172
#define EDGE_D  172
#define TIME_D  100
#define QD      272      // NODE_D + TIME_D
#define KD      444      // NODE_D + EDGE_D + TIME_D
#define NHEAD   2
#define HD      136      // QD / NHEAD
#define KD2     888      // NHEAD * KD
#define SCALE   0.08574929257125441f   // 136^-0.5
#define LN_EPS  1e-5f

// ---------------- scratch (device globals; no runtime alloc) ----------------
__device__ float g_M [QD * KD2];          // M[i][h*444+j]  (272 x 888)
__device__ float g_P [KD2 * QD];          // P[h*444+j][c]  (888 x 272)
__device__ float g_QK[(size_t)BATCH * KD2];   // 71 MB
__device__ float g_WS[(size_t)BATCH * KD2];   // 71 MB
__device__ float g_YP[(size_t)BATCH * QD];    // 21.8 MB

// ---------------- weight folding (both folded mats in one launch) ----------
// M[i][hj] = sum_d Wq[(h*136+d)*272 + i] * Wk[(h*136+d)*444 + j]
// P[hj][c] = sum_d Wv[(h*136+d)*444 + j] * Wr[c*272 + h*136 + d]
__global__ void fold_MP(const float* __restrict__ Wq, const float* __restrict__ Wk,
                        const float* __restrict__ Wv, const float* __restrict__ Wr) {
    int t = blockIdx.x * blockDim.x + threadIdx.x;
    const int TOT = QD * KD2;
    if (t < TOT) {
        int i  = t / KD2;
        int hj = t - i * KD2;
        int h  = hj / KD;
        int j  = hj - h * KD;
        const float* wq = Wq + (size_t)(h * HD) * QD + i;   // stride QD
        const float* wk = Wk + (size_t)(h * HD) * KD + j;   // stride KD
        float s = 0.f;
        #pragma unroll 4
        for (int d = 0; d < HD; ++d) s += wq[(size_t)d * QD] * wk[(size_t)d * KD];
        g_M[t] = s;
    } else if (t < 2 * TOT) {
        t -= TOT;
        int c  = t / KD2;
        int hj = t - c * KD2;
        int h  = hj / KD;
        int j  = hj - h * KD;
        const float* wv = Wv + (size_t)(h * HD) * KD + j;   // stride KD
        const float* wr = Wr + (size_t)c * QD + h * HD;     // stride 1
        float s = 0.f;
        #pragma unroll 4
        for (int d = 0; d < HD; ++d) s += wv[(size_t)d * KD] * wr[d];
        g_P[(size_t)hj * QD + c] = s;
    }
}

// ---------------- GEMM 1: QK = q_in[20000,272] @ M[272,888] ----------------
// q_in gathered: col i<172 -> node_features, else node_time_features
__global__ __launch_bounds__(256) void gemm_qk(const float* __restrict__ nf,
                                               const float* __restrict__ ntf) {
    __shared__ float As[8][128];
    __shared__ float Bs[8][128];
    const int tid = threadIdx.x;
    const int m0 = blockIdx.y * 128;
    const int n0 = blockIdx.x * 128;
    const int tx = tid & 15, ty = tid >> 4;
    const int ar = tid >> 1;            // row in A tile
    const int ac = (tid & 1) * 4;       // col-quad in A tile
    const int brr = tid >> 5;           // row in B tile
    const int bc  = (tid & 31) * 4;     // col-quad in B tile

    float acc[8][8];
    #pragma unroll
    for (int i = 0; i < 8; ++i)
        #pragma unroll
        for (int j = 0; j < 8; ++j) acc[i][j] = 0.f;

    for (int k0 = 0; k0 < QD; k0 += 8) {
        // A tile (gathered concat), store transposed As[k][m]
        {
            int grow = m0 + ar;
            #pragma unroll
            for (int u = 0; u < 4; ++u) {
                int i = k0 + ac + u;     // < 272 always
                float v = 0.f;
                if (grow < BATCH)
                    v = (i < NODE_D) ? nf[(size_t)grow * NODE_D + i]
                                     : ntf[(size_t)grow * TIME_D + (i - NODE_D)];
                As[ac + u][ar] = v;
            }
        }
        // B tile
        {
            int col = n0 + bc;
            float4 v = make_float4(0.f, 0.f, 0.f, 0.f);
            if (col + 3 < KD2) {
                v = *(const float4*)&g_M[(size_t)(k0 + brr) * KD2 + col];
            } else {
                float* pv = &v.x;
                #pragma unroll
                for (int u = 0; u < 4; ++u)
                    if (col + u < KD2) pv[u] = g_M[(size_t)(k0 + brr) * KD2 + col + u];
            }
            *(float4*)&Bs[brr][bc] = v;
        }
        __syncthreads();
        #pragma unroll
        for (int k = 0; k < 8; ++k) {
            float a[8], b[8];
            *(float4*)(a)     = *(const float4*)&As[k][ty * 4];
            *(float4*)(a + 4) = *(const float4*)&As[k][ty * 4 + 64];
            *(float4*)(b)     = *(const float4*)&Bs[k][tx * 4];
            *(float4*)(b + 4) = *(const float4*)&Bs[k][tx * 4 + 64];
            #pragma unroll
            for (int i = 0; i < 8; ++i)
                #pragma unroll
                for (int j = 0; j < 8; ++j) acc[i][j] += a[i] * b[j];
        }
        __syncthreads();
    }
    #pragma unroll
    for (int i = 0; i < 8; ++i) {
        int row = m0 + ty * 4 + (i & 3) + (i >> 2) * 64;
        if (row >= BATCH) continue;
        #pragma unroll
        for (int j = 0; j < 8; ++j) {
            int col = n0 + tx * 4 + (j & 3) + (j >> 2) * 64;
            if (col < KD2) g_QK[(size_t)row * KD2 + col] = acc[i][j];
        }
    }
}

// ---------------- Attention streaming kernel (one CTA per root) ----------------
__global__ __launch_bounds__(256) void attn_kernel(const float* __restrict__ nbf,
                                                   const float* __restrict__ nbe,
                                                   const float* __restrict__ nbt,
                                                   const int*   __restrict__ masks,
                                                   float* __restrict__ out_attn) {
    const int b = blockIdx.x;
    __shared__ float kv[NNB][448];     // padded 444->448
    __shared__ float qk[KD2];
    __shared__ float sc[NHEAD][32];
    __shared__ float at[NHEAD][NNB];
    const int tid = threadIdx.x;

    for (int e = tid; e < KD2; e += 256) qk[e] = g_QK[(size_t)b * KD2 + e];

    const float* f1 = nbf + (size_t)b * NNB * NODE_D;
    const float* f2 = nbe + (size_t)b * NNB * EDGE_D;
    const float* f3 = nbt + (size_t)b * NNB * TIME_D;
    for (int e = tid; e < NNB * KD; e += 256) {
        int n = e / KD, j = e - n * KD;
        float v;
        if (j < NODE_D)             v = f1[n * NODE_D + j];
        else if (j < NODE_D+EDGE_D) v = f2[n * EDGE_D + (j - NODE_D)];
        else                        v = f3[n * TIME_D + (j - NODE_D - EDGE_D)];
        kv[n][j] = v;
    }
    __syncthreads();

    const int warp = tid >> 5, lane = tid & 31;
    // 40 (head, neighbor) dot products over 8 warps
    for (int dot = warp; dot < NHEAD * NNB; dot += 8) {
        int h = dot / NNB, n = dot - h * NNB;
        const float* qkh = qk + h * KD;
        float s = 0.f;
        for (int j = lane; j < KD; j += 32) s += kv[n][j] * qkh[j];
        #pragma unroll
        for (int o = 16; o; o >>= 1) s += __shfl_xor_sync(0xFFFFFFFFu, s, o);
        if (lane == 0) {
            s *= SCALE;
            if (masks[b * NNB + n] == 0) s = -1e10f;
            sc[h][n] = s;
        }
    }
    __syncthreads();
    if (warp < NHEAD) {
        const int h = warp;
        float s = (lane < NNB) ? sc[h][lane] : -3.0e38f;
        float m = s;
        #pragma unroll
        for (int o = 16; o; o >>= 1) m = fmaxf(m, __shfl_xor_sync(0xFFFFFFFFu, m, o));
        float e = (lane < NNB) ? __expf(s - m) : 0.f;
        float sum = e;
        #pragma unroll
        for (int o = 16; o; o >>= 1) sum += __shfl_xor_sync(0xFFFFFFFFu, sum, o);
        float a = e / sum;
        if (lane < NNB) {
            at[h][lane] = a;
            out_attn[(size_t)b * (NHEAD * NNB) + h * NNB + lane] = a;
        }
    }
    __syncthreads();
    // weighted sum of kv rows per head
    for (int o = tid; o < KD2; o += 256) {
        int h = o / KD, j = o - h * KD;
        float acc = 0.f;
        #pragma unroll
        for (int n = 0; n < NNB; ++n) acc += at[h][n] * kv[n][j];
        g_WS[(size_t)b * KD2 + o] = acc;
    }
}

// ---------------- GEMM 2: YP = WS[20000,888] @ P[888,272] ----------------
__global__ __launch_bounds__(256) void gemm_out() {
    __shared__ float As[8][128];
    __shared__ float Bs[8][96];
    const int tid = threadIdx.x;
    const int m0 = blockIdx.y * 128;
    const int n0 = blockIdx.x * 96;
    const int tx = tid & 15, ty = tid >> 4;

    float acc[8][6];
    #pragma unroll
    for (int i = 0; i < 8; ++i)
        #pragma unroll
        for (int j = 0; j < 6; ++j) acc[i][j] = 0.f;

    for (int k0 = 0; k0 < KD2; k0 += 8) {
        // A tile (contiguous), transposed store
        {
            int grow = m0 + (tid >> 1);
            float4 av = make_float4(0.f, 0.f, 0.f, 0.f);
            if (grow < BATCH)
                av = *(const float4*)&g_WS[(size_t)grow * KD2 + k0 + (tid & 1) * 4];
            int kc = (tid & 1) * 4, r = tid >> 1;
            As[kc + 0][r] = av.x;
            As[kc + 1][r] = av.y;
            As[kc + 2][r] = av.z;
            As[kc + 3][r] = av.w;
        }
        // B tile: 8 x 96 = 768 elems, 3 per thread
        #pragma unroll
        for (int q = 0; q < 3; ++q) {
            int e = tid + q * 256;
            int r = e / 96, c = e - r * 96;
            int col = n0 + c;
            Bs[r][c] = (col < QD) ? g_P[(size_t)(k0 + r) * QD + col] : 0.f;
        }
        __syncthreads();
        #pragma unroll
        for (int k = 0; k < 8; ++k) {
            float a[8], b[6];
            *(float4*)(a)     = *(const float4*)&As[k][ty * 4];
            *(float4*)(a + 4) = *(const float4*)&As[k][ty * 4 + 64];
            #pragma unroll
            for (int u = 0; u < 3; ++u) {
                b[u]     = Bs[k][tx * 3 + u];
                b[3 + u] = Bs[k][48 + tx * 3 + u];
            }
            #pragma unroll
            for (int i = 0; i < 8; ++i)
                #pragma unroll
                for (int j = 0; j < 6; ++j) acc[i][j] += a[i] * b[j];
        }
        __syncthreads();
    }
    #pragma unroll
    for (int i = 0; i < 8; ++i) {
        int row = m0 + ty * 4 + (i & 3) + (i >> 2) * 64;
        if (row >= BATCH) continue;
        #pragma unroll
        for (int j = 0; j < 6; ++j) {
            int col = n0 + tx * 3 + (j % 3) + (j / 3) * 48;
            if (col < QD) g_YP[(size_t)row * QD + col] = acc[i][j];
        }
    }
}

// ---------------- Residual + bias + LayerNorm (one warp per row) ----------------
__global__ __launch_bounds__(256) void ln_kernel(const float* __restrict__ nf,
                                                 const float* __restrict__ ntf,
                                                 const float* __restrict__ br,
                                                 const float* __restrict__ gamma,
                                                 const float* __restrict__ beta,
                                                 float* __restrict__ out) {
    int row = blockIdx.x * 8 + (threadIdx.x >> 5);
    int lane = threadIdx.x & 31;
    if (row >= BATCH) return;
    float x[9];
    float sum = 0.f, sq = 0.f;
    #pragma unroll
    for (int i = 0; i < 9; ++i) {
        int c = lane + 32 * i;
        float v = 0.f;
        if (c < QD) {
            float r = (c < NODE_D) ? nf[(size_t)row * NODE_D + c]
                                   : ntf[(size_t)row * TIME_D + (c - NODE_D)];
            v = g_YP[(size_t)row * QD + c] + br[c] + r;
        }
        x[i] = v;
        sum += v;
        sq  += v * v;
    }
    #pragma unroll
    for (int o = 16; o; o >>= 1) {
        sum += __shfl_xor_sync(0xFFFFFFFFu, sum, o);
        sq  += __shfl_xor_sync(0xFFFFFFFFu, sq,  o);
    }
    const float inv_n = 1.f / (float)QD;
    float mu  = sum * inv_n;
    float var = sq * inv_n - mu * mu;
    float inv = rsqrtf(var + LN_EPS);
    #pragma unroll
    for (int i = 0; i < 9; ++i) {
        int c = lane + 32 * i;
        if (c < QD)
            out[(size_t)row * QD + c] = (x[i] - mu) * inv * gamma[c] + beta[c];
    }
}

// ---------------- launch ----------------
extern "C" void kernel_launch(void* const* d_in, const int* in_sizes, int n_in,
                              void* d_out, int out_size) {
    const float* nf   = (const float*)d_in[0];   // node_features        [B,172]
    const float* ntf  = (const float*)d_in[1];   // node_time_features   [B,1,100]
    const float* nbf  = (const float*)d_in[2];   // neighbor_node_features [B,N,172]
    const float* nbt  = (const float*)d_in[3];   // neighbor_node_time   [B,N,100]
    const float* nbe  = (const float*)d_in[4];   // neighbor_node_edge   [B,N,172]
    const int*   mask = (const int*)  d_in[5];   // neighbor_masks       [B,N]
    const float* Wq   = (const float*)d_in[6];
    const float* Wk   = (const float*)d_in[7];
    const float* Wv   = (const float*)d_in[8];
    const float* Wr   = (const float*)d_in[9];
    const float* br   = (const float*)d_in[10];
    const float* gamma= (const float*)d_in[11];
    const float* beta = (const float*)d_in[12];

    float* out1 = (float*)d_out;                         // [B, 272]
    float* out2 = out1 + (size_t)BATCH * QD;             // [B, 2, 20]

    const int fold_threads = 2 * QD * KD2;
    fold_MP<<<(fold_threads + 255) / 256, 256>>>(Wq, Wk, Wv, Wr);

    gemm_qk<<<dim3((KD2 + 127) / 128, (BATCH + 127) / 128), 256>>>(nf, ntf);

    attn_kernel<<<BATCH, 256>>>(nbf, nbe, nbt, mask, out2);

    gemm_out<<<dim3((QD + 95) / 96, (BATCH + 127) / 128), 256>>>();

    ln_kernel<<<(BATCH + 7) / 8, 256>>>(nf, ntf, br, gamma, beta, out1);
}

// round 11
// speedup vs baseline: 1.4411x; 1.4411x over previous
#include <cuda_runtime.h>
#include <cuda_bf16.h>
#include <cstdint>

// Problem constants
#define BATCH   20000
#define NNB     20
#define NODE_D  172
#define EDGE_D  172
#define TIME_D  100
#define QD      272      // NODE_D + TIME_D
#define KD      444      // NODE_D + EDGE_D + TIME_D
#define NHEAD   2
#define HD      136      // QD / NHEAD
#define KD2     888      // NHEAD * KD
#define KP2     896      // KD2 padded to multiple of 64
#define NP1     896      // GEMM1 N (888) padded to multiple of 128
#define NP2     384      // GEMM2 N (272) padded to multiple of 128
#define SCALE   0.08574929257125441f   // 136^-0.5
#define LN_EPS  1e-5f

// ---------------- scratch (device globals; no runtime alloc) ----------------
__device__ float g_QK [(size_t)BATCH * KD2];    // 71 MB
__device__ float g_YP [(size_t)BATCH * QD];     // 21.8 MB
__device__ __align__(16) __nv_bfloat16  g_A1h[(size_t)BATCH * QD];
__device__ __align__(16) __nv_bfloat16  g_A1l[(size_t)BATCH * QD];
__device__ __align__(16) __nv_bfloat16  g_WSh[(size_t)BATCH * KP2];
__device__ __align__(16) __nv_bfloat16  g_WSl[(size_t)BATCH * KP2];
__device__ __align__(16) __nv_bfloat16  g_B1h[(size_t)NP1 * QD];
__device__ __align__(16) __nv_bfloat16  g_B1l[(size_t)NP1 * QD];
__device__ __align__(16) __nv_bfloat16  g_B2h[(size_t)NP2 * KP2];
__device__ __align__(16) __nv_bfloat16  g_B2l[(size_t)NP2 * KP2];

// ---------------- helpers (all baseline sm_80+ features) ----------------
__device__ __forceinline__ uint32_t smem_u32(const void* p) {
    uint32_t a;
    asm("{ .reg .u64 t; cvta.to.shared.u64 t, %1; cvt.u32.u64 %0, t; }" : "=r"(a) : "l"(p));
    return a;
}
__device__ __forceinline__ uint32_t swz(uint32_t off) { return off ^ ((off >> 3) & 0x70); }

__device__ __forceinline__ void cp16(uint32_t dst, const void* src, int srcsz) {
    asm volatile("cp.async.cg.shared.global [%0], [%1], 16, %2;"
                 :: "r"(dst), "l"(src), "r"(srcsz));
}
__device__ __forceinline__ void cp_commit() {
    asm volatile("cp.async.commit_group;" ::: "memory");
}
__device__ __forceinline__ void cp_wait1() {
    asm volatile("cp.async.wait_group 1;" ::: "memory");
}

__device__ __forceinline__ void ldm4(uint32_t* r, uint32_t addr) {
    asm volatile("ldmatrix.sync.aligned.m8n8.x4.shared.b16 {%0,%1,%2,%3}, [%4];"
                 : "=r"(r[0]), "=r"(r[1]), "=r"(r[2]), "=r"(r[3]) : "r"(addr));
}
__device__ __forceinline__ void mma16816(float* c, const uint32_t* a, uint32_t b0, uint32_t b1) {
    asm volatile("mma.sync.aligned.m16n8k16.row.col.f32.bf16.bf16.f32 "
                 "{%0,%1,%2,%3}, {%4,%5,%6,%7}, {%8,%9}, {%0,%1,%2,%3};"
                 : "+f"(c[0]), "+f"(c[1]), "+f"(c[2]), "+f"(c[3])
                 : "r"(a[0]), "r"(a[1]), "r"(a[2]), "r"(a[3]), "r"(b0), "r"(b1));
}

__device__ __forceinline__ void split_bf16(float x, __nv_bfloat16& h, __nv_bfloat16& l) {
    h = __float2bfloat16(x);
    l = __float2bfloat16(x - __bfloat162float(h));
}

// ---------------- prep: q_in gather + bf16 split ----------------
__global__ void prep_q(const float* __restrict__ nf, const float* __restrict__ ntf) {
    int t = blockIdx.x * blockDim.x + threadIdx.x;
    if (t >= BATCH * QD) return;
    int b = t / QD, k = t - b * QD;
    float x = (k < NODE_D) ? nf[(size_t)b * NODE_D + k]
                           : ntf[(size_t)b * TIME_D + (k - NODE_D)];
    __nv_bfloat16 h, l;
    split_bf16(x, h, l);
    g_A1h[t] = h; g_A1l[t] = l;
}

// ---------------- fold: B1[n=hj][k=i], B2[n=c][k=hj], bf16 split ----------
__global__ void fold_MP(const float* __restrict__ Wq, const float* __restrict__ Wk,
                        const float* __restrict__ Wv, const float* __restrict__ Wr) {
    int t = blockIdx.x * blockDim.x + threadIdx.x;
    const int T1 = NP1 * QD;
    const int T2 = NP2 * KP2;
    if (t < T1) {
        int n = t / QD, k = t - n * QD;
        float s = 0.f;
        if (n < KD2) {
            int h = n / KD, j = n - h * KD;
            const float* wq = Wq + (size_t)(h * HD) * QD + k;
            const float* wk = Wk + (size_t)(h * HD) * KD + j;
            #pragma unroll 4
            for (int d = 0; d < HD; ++d) s += wq[(size_t)d * QD] * wk[(size_t)d * KD];
        }
        __nv_bfloat16 hh, ll; split_bf16(s, hh, ll);
        g_B1h[t] = hh; g_B1l[t] = ll;
    } else if (t < T1 + T2) {
        int t2 = t - T1;
        int n = t2 / KP2, k = t2 - n * KP2;
        float s = 0.f;
        if (n < QD && k < KD2) {
            int h = k / KD, j = k - h * KD;
            const float* wv = Wv + (size_t)(h * HD) * KD + j;
            const float* wr = Wr + (size_t)n * QD + h * HD;
            #pragma unroll 4
            for (int d = 0; d < HD; ++d) s += wv[(size_t)d * KD] * wr[d];
        }
        __nv_bfloat16 hh, ll; split_bf16(s, hh, ll);
        g_B2h[t2] = hh; g_B2l[t2] = ll;
    }
}

// ---------------- mma.sync GEMM: C[M,N] = A[M,K] @ B[N,K]^T (bf16 split-3) --
// CTA tile 128x128, 8 warps in 2x4 (warp tile 64x32).
// K staged in chunks of 64 bf16 (128B SW128 rows), cp.async double buffer.
// SMEM per stage: 4 mats (Ah, Al, Bh, Bl) x 128 rows x 128B = 64 KB.
#define GEMM_SMEM_BYTES (2 * 65536)

// ldmatrix address: A-layout tile (m16 x k16) at rows a0.., k-byte kb
__device__ __forceinline__ uint32_t a_addr(uint32_t mb, int a0, int kb, int lane) {
    int quad = lane >> 3, rl = lane & 7;
    int row = a0 + ((quad & 1) << 3) + rl;
    int kk  = kb + ((quad >> 1) << 4);
    return mb + swz(row * 128 + kk);
}
// B tile (n16 x k16): matrices {n0-7/kb, n0-7/kb+16, n8-15/kb, n8-15/kb+16}
__device__ __forceinline__ uint32_t b_addr(uint32_t mb, int b0, int kb, int lane) {
    int quad = lane >> 3, rl = lane & 7;
    int row = b0 + ((quad >> 1) << 3) + rl;
    int kk  = kb + ((quad & 1) << 4);
    return mb + swz(row * 128 + kk);
}

template <int SEL>
__global__ __launch_bounds__(256) void mma_gemm() {
    constexpr int KDIM   = SEL ? KP2 : QD;     // 896 / 272
    constexpr int NCHUNK = SEL ? 14  : 5;
    constexpr int KSTEPS = SEL ? 56  : 17;     // k16 steps
    constexpr int NREAL  = SEL ? QD  : KD2;    // valid C cols

    extern __shared__ char smem[];
    const uint32_t sbase = smem_u32(smem);
    const int tid  = threadIdx.x;
    const int wid  = tid >> 5;
    const int lane = tid & 31;
    const int m0 = blockIdx.y * 128;
    const int n0 = blockIdx.x * 128;
    const int mw = (wid & 1) * 64;    // warp m-offset within tile
    const int nw = (wid >> 1) * 32;   // warp n-offset within tile

    const __nv_bfloat16* __restrict__ Ah = SEL ? g_WSh : g_A1h;
    const __nv_bfloat16* __restrict__ Al = SEL ? g_WSl : g_A1l;
    const __nv_bfloat16* __restrict__ Bh = SEL ? g_B2h : g_B1h;
    const __nv_bfloat16* __restrict__ Bl = SEL ? g_B2l : g_B1l;
    float* __restrict__ Cout = SEL ? g_YP : g_QK;

    // --- stage issue: chunk c -> buffer buf (16 cp.async of 16B per thread)
    auto issue = [&](int c, int buf) {
        const int k0 = c * 64;
        const uint32_t so = sbase + buf * 65536;
        #pragma unroll
        for (int i = 0; i < 16; ++i) {
            int e   = tid + i * 256;
            int mat = e >> 10;
            int r   = (e >> 3) & 127;
            int q   = e & 7;
            int gk  = k0 + q * 8;
            const __nv_bfloat16* src;
            int ok = (gk + 8 <= KDIM);
            if (mat < 2) {
                int row = m0 + r;
                ok = ok && (row < BATCH);
                const __nv_bfloat16* base = (mat == 0) ? Ah : Al;
                src = ok ? base + (size_t)row * KDIM + gk : base;
            } else {
                int row = n0 + r;
                const __nv_bfloat16* base = (mat == 2) ? Bh : Bl;
                src = ok ? base + (size_t)row * KDIM + gk : base;
            }
            cp16(so + mat * 16384 + swz(r * 128 + q * 16), src, ok ? 16 : 0);
        }
    };

    float acc[4][4][4];
    #pragma unroll
    for (int i = 0; i < 4; ++i)
        #pragma unroll
        for (int j = 0; j < 4; ++j)
            #pragma unroll
            for (int u = 0; u < 4; ++u) acc[i][j][u] = 0.f;

    issue(0, 0); cp_commit();

    for (int c = 0; c < NCHUNK; ++c) {
        if (c + 1 < NCHUNK) issue(c + 1, (c + 1) & 1);
        cp_commit();
        cp_wait1();
        __syncthreads();

        const uint32_t so = sbase + (c & 1) * 65536;
        const uint32_t mAh = so, mAl = so + 16384, mBh = so + 32768, mBl = so + 49152;
        const int nks = (KSTEPS - c * 4 < 4) ? (KSTEPS - c * 4) : 4;

        for (int ks = 0; ks < nks; ++ks) {
            const int kb = ks * 32;
            uint32_t A[4][4], B[2][4];
            // pass 1: Ah . Bh
            #pragma unroll
            for (int i = 0; i < 4; ++i) ldm4(A[i], a_addr(mAh, mw + 16 * i, kb, lane));
            #pragma unroll
            for (int jj = 0; jj < 2; ++jj) ldm4(B[jj], b_addr(mBh, nw + 16 * jj, kb, lane));
            #pragma unroll
            for (int i = 0; i < 4; ++i)
                #pragma unroll
                for (int j = 0; j < 4; ++j)
                    mma16816(acc[i][j], A[i], B[j >> 1][(j & 1) * 2], B[j >> 1][(j & 1) * 2 + 1]);
            // pass 2: Ah . Bl
            #pragma unroll
            for (int jj = 0; jj < 2; ++jj) ldm4(B[jj], b_addr(mBl, nw + 16 * jj, kb, lane));
            #pragma unroll
            for (int i = 0; i < 4; ++i)
                #pragma unroll
                for (int j = 0; j < 4; ++j)
                    mma16816(acc[i][j], A[i], B[j >> 1][(j & 1) * 2], B[j >> 1][(j & 1) * 2 + 1]);
            // pass 3: Al . Bh
            #pragma unroll
            for (int i = 0; i < 4; ++i) ldm4(A[i], a_addr(mAl, mw + 16 * i, kb, lane));
            #pragma unroll
            for (int jj = 0; jj < 2; ++jj) ldm4(B[jj], b_addr(mBh, nw + 16 * jj, kb, lane));
            #pragma unroll
            for (int i = 0; i < 4; ++i)
                #pragma unroll
                for (int j = 0; j < 4; ++j)
                    mma16816(acc[i][j], A[i], B[j >> 1][(j & 1) * 2], B[j >> 1][(j & 1) * 2 + 1]);
        }
        __syncthreads();
    }

    // epilogue: D frag -> global. lane t: rows t/4, t/4+8; cols (t%4)*2, +1
    const int rbase = m0 + mw + (lane >> 2);
    const int cbase = n0 + nw + (lane & 3) * 2;
    #pragma unroll
    for (int i = 0; i < 4; ++i) {
        #pragma unroll
        for (int j = 0; j < 4; ++j) {
            int col = cbase + 8 * j;
            if (col >= NREAL) continue;
            int r0 = rbase + 16 * i;
            if (r0 < BATCH) {
                float2 v = make_float2(acc[i][j][0], acc[i][j][1]);
                *(float2*)(Cout + (size_t)r0 * NREAL + col) = v;
            }
            if (r0 + 8 < BATCH) {
                float2 v = make_float2(acc[i][j][2], acc[i][j][3]);
                *(float2*)(Cout + (size_t)(r0 + 8) * NREAL + col) = v;
            }
        }
    }
}

// ---------------- Attention streaming kernel (one CTA per root) ----------------
__global__ __launch_bounds__(256) void attn_kernel(const float* __restrict__ nbf,
                                                   const float* __restrict__ nbe,
                                                   const float* __restrict__ nbt,
                                                   const int*   __restrict__ masks,
                                                   float* __restrict__ out_attn) {
    const int b = blockIdx.x;
    __shared__ float kv[NNB][448];
    __shared__ float qk[KD2];
    __shared__ float sc[NHEAD][32];
    __shared__ float at[NHEAD][NNB];
    const int tid = threadIdx.x;

    for (int e = tid; e < KD2; e += 256) qk[e] = g_QK[(size_t)b * KD2 + e];

    const float* f1 = nbf + (size_t)b * NNB * NODE_D;
    const float* f2 = nbe + (size_t)b * NNB * EDGE_D;
    const float* f3 = nbt + (size_t)b * NNB * TIME_D;
    for (int e = tid; e < NNB * KD; e += 256) {
        int n = e / KD, j = e - n * KD;
        float v;
        if (j < NODE_D)             v = f1[n * NODE_D + j];
        else if (j < NODE_D+EDGE_D) v = f2[n * EDGE_D + (j - NODE_D)];
        else                        v = f3[n * TIME_D + (j - NODE_D - EDGE_D)];
        kv[n][j] = v;
    }
    __syncthreads();

    const int warp = tid >> 5, lane = tid & 31;
    for (int dot = warp; dot < NHEAD * NNB; dot += 8) {
        int h = dot / NNB, n = dot - h * NNB;
        const float* qkh = qk + h * KD;
        float s = 0.f;
        for (int j = lane; j < KD; j += 32) s += kv[n][j] * qkh[j];
        #pragma unroll
        for (int o = 16; o; o >>= 1) s += __shfl_xor_sync(0xFFFFFFFFu, s, o);
        if (lane == 0) {
            s *= SCALE;
            if (masks[b * NNB + n] == 0) s = -1e10f;
            sc[h][n] = s;
        }
    }
    __syncthreads();
    if (warp < NHEAD) {
        const int h = warp;
        float s = (lane < NNB) ? sc[h][lane] : -3.0e38f;
        float m = s;
        #pragma unroll
        for (int o = 16; o; o >>= 1) m = fmaxf(m, __shfl_xor_sync(0xFFFFFFFFu, m, o));
        float e = (lane < NNB) ? __expf(s - m) : 0.f;
        float sum = e;
        #pragma unroll
        for (int o = 16; o; o >>= 1) sum += __shfl_xor_sync(0xFFFFFFFFu, sum, o);
        float a = e / sum;
        if (lane < NNB) {
            at[h][lane] = a;
            out_attn[(size_t)b * (NHEAD * NNB) + h * NNB + lane] = a;
        }
    }
    __syncthreads();
    for (int o = tid; o < KP2; o += 256) {
        float acc = 0.f;
        if (o < KD2) {
            int h = o / KD, j = o - h * KD;
            #pragma unroll
            for (int n = 0; n < NNB; ++n) acc += at[h][n] * kv[n][j];
        }
        __nv_bfloat16 hh, ll; split_bf16(acc, hh, ll);
        g_WSh[(size_t)b * KP2 + o] = hh;
        g_WSl[(size_t)b * KP2 + o] = ll;
    }
}

// ---------------- Residual + bias + LayerNorm (one warp per row) ----------------
__global__ __launch_bounds__(256) void ln_kernel(const float* __restrict__ nf,
                                                 const float* __restrict__ ntf,
                                                 const float* __restrict__ br,
                                                 const float* __restrict__ gamma,
                                                 const float* __restrict__ beta,
                                                 float* __restrict__ out) {
    int row = blockIdx.x * 8 + (threadIdx.x >> 5);
    int lane = threadIdx.x & 31;
    if (row >= BATCH) return;
    float x[9];
    float sum = 0.f, sq = 0.f;
    #pragma unroll
    for (int i = 0; i < 9; ++i) {
        int c = lane + 32 * i;
        float v = 0.f;
        if (c < QD) {
            float r = (c < NODE_D) ? nf[(size_t)row * NODE_D + c]
                                   : ntf[(size_t)row * TIME_D + (c - NODE_D)];
            v = g_YP[(size_t)row * QD + c] + br[c] + r;
        }
        x[i] = v;
        sum += v;
        sq  += v * v;
    }
    #pragma unroll
    for (int o = 16; o; o >>= 1) {
        sum += __shfl_xor_sync(0xFFFFFFFFu, sum, o);
        sq  += __shfl_xor_sync(0xFFFFFFFFu, sq,  o);
    }
    const float inv_n = 1.f / (float)QD;
    float mu  = sum * inv_n;
    float var = sq * inv_n - mu * mu;
    float inv = rsqrtf(var + LN_EPS);
    #pragma unroll
    for (int i = 0; i < 9; ++i) {
        int c = lane + 32 * i;
        if (c < QD)
            out[(size_t)row * QD + c] = (x[i] - mu) * inv * gamma[c] + beta[c];
    }
}

// ---------------- launch ----------------
extern "C" void kernel_launch(void* const* d_in, const int* in_sizes, int n_in,
                              void* d_out, int out_size) {
    const float* nf   = (const float*)d_in[0];
    const float* ntf  = (const float*)d_in[1];
    const float* nbf  = (const float*)d_in[2];
    const float* nbt  = (const float*)d_in[3];
    const float* nbe  = (const float*)d_in[4];
    const int*   mask = (const int*)  d_in[5];
    const float* Wq   = (const float*)d_in[6];
    const float* Wk   = (const float*)d_in[7];
    const float* Wv   = (const float*)d_in[8];
    const float* Wr   = (const float*)d_in[9];
    const float* br   = (const float*)d_in[10];
    const float* gamma= (const float*)d_in[11];
    const float* beta = (const float*)d_in[12];

    float* out1 = (float*)d_out;                         // [B, 272]
    float* out2 = out1 + (size_t)BATCH * QD;             // [B, 2, 20]

    cudaFuncSetAttribute(mma_gemm<0>, cudaFuncAttributeMaxDynamicSharedMemorySize, GEMM_SMEM_BYTES);
    cudaFuncSetAttribute(mma_gemm<1>, cudaFuncAttributeMaxDynamicSharedMemorySize, GEMM_SMEM_BYTES);

    prep_q<<<(BATCH * QD + 255) / 256, 256>>>(nf, ntf);

    const int fold_threads = NP1 * QD + NP2 * KP2;
    fold_MP<<<(fold_threads + 255) / 256, 256>>>(Wq, Wk, Wv, Wr);

    // GEMM1: g_QK[20000,888] = A1[20000,272] @ B1[896,272]^T
    mma_gemm<0><<<dim3(NP1 / 128, (BATCH + 127) / 128), 256, GEMM_SMEM_BYTES>>>();

    attn_kernel<<<BATCH, 256>>>(nbf, nbe, nbt, mask, out2);

    // GEMM2: g_YP[20000,272] = WS[20000,896] @ B2[384,896]^T
    mma_gemm<1><<<dim3(NP2 / 128, (BATCH + 127) / 128), 256, GEMM_SMEM_BYTES>>>();

    ln_kernel<<<(BATCH + 7) / 8, 256>>>(nf, ntf, br, gamma, beta, out1);
}